// round 4
// baseline (speedup 1.0000x reference)
#include <cuda_runtime.h>
#include <math.h>

#define TT 32
#define DD 256
#define HH 768
#define GRIDN 128
#define NT 256

#define OFF_HXLAST (TT*128*HH)
#define OFF_PC     (OFF_HXLAST + 128*HH)
#define OFF_STEPS  (OFF_PC + 128)

typedef unsigned long long ull;

// persistent scratch (allocation-free rule)
__device__ float g_hxi[2][128][HH];              // double-buffered hidden state
__device__ float g_pd[8*128*32];                 // partial ponder dots [n][row][cg]
__device__ __align__(16) unsigned g_flags[GRIDN];// barrier flags (monotonic)

struct SM {
  ull   whh[HH*16];      // [k][16 slots] swizzled col-pairs, 98304 B
  ull   wih[DD*16];      // same layout for K<256, 32768 B
  float base[32][26];
  float hxn[32][26];
  float ahx[32][26];
  float flagw[24], wp[24], bias[24];
  float ah[128], sc[128], spc[128], coef[128], pc[128];
  int   mask[128];
};

__device__ __forceinline__ ull fma2(ull a, ull b, ull c){
  ull d; asm("fma.rn.f32x2 %0,%1,%2,%3;" : "=l"(d) : "l"(a), "l"(b), "l"(c)); return d;
}
__device__ __forceinline__ ull add2(ull a, ull b){
  ull d; asm("add.rn.f32x2 %0,%1,%2;" : "=l"(d) : "l"(a), "l"(b)); return d;
}
__device__ __forceinline__ ull dup2(float x){
  ull d; unsigned r = __float_as_uint(x);
  asm("mov.b64 %0,{%1,%1};" : "=l"(d) : "r"(r)); return d;
}
__device__ __forceinline__ ull shx64(ull v, int m){
  unsigned lo = (unsigned)v, hi = (unsigned)(v >> 32);
  lo = __shfl_xor_sync(0xffffffffu, lo, m);
  hi = __shfl_xor_sync(0xffffffffu, hi, m);
  return ((ull)hi << 32) | lo;
}

// flag-based grid barrier: 1 release STG arrival, 32 pollers x 4 flags
__device__ __forceinline__ void gbar(unsigned ep){
  __syncthreads();
  if (threadIdx.x == 0)
    asm volatile("st.release.gpu.global.u32 [%0], %1;"
                 :: "l"(&g_flags[blockIdx.x]), "r"(ep) : "memory");
  if (threadIdx.x < 32){
    const unsigned* fp = g_flags + threadIdx.x*4;
    for(;;){
      unsigned a,b,c,d;
      asm volatile("ld.relaxed.gpu.global.v4.u32 {%0,%1,%2,%3}, [%4];"
                   : "=r"(a),"=r"(b),"=r"(c),"=r"(d) : "l"(fp) : "memory");
      if ((int)(a-ep)>=0 && (int)(b-ep)>=0 && (int)(c-ep)>=0 && (int)(d-ep)>=0) break;
    }
    asm volatile("fence.acq_rel.gpu;" ::: "memory");
  }
  __syncthreads();
}

// warp tile: 8 rows (og=lane>>2) x 6 col-pairs (pg6), K split 4-way (kl=lane&3)
// k = it*16 + kl*4 + j. Weights: slot(p,k) = (p + 2*((k>>2)&7)) & 15.
template<int NIT, bool CG>
__device__ __forceinline__ void gemm6(ull (&acc)[6], const float* __restrict__ xrow,
                                      const ull* W, int kl, int pg6){
  const float4* xp = (const float4*)xrow;
  float4 xa, xb, xc;
  xa = CG ? __ldcg(xp + kl) : __ldg(xp + kl);
  xb = CG ? __ldcg(xp + 4 + kl) : __ldg(xp + 4 + kl);
  #pragma unroll 4
  for (int it = 0; it < NIT; ++it){
    if (it + 2 < NIT) xc = CG ? __ldcg(xp + (it+2)*4 + kl) : __ldg(xp + (it+2)*4 + kl);
    int r2 = ((it*4 + kl) & 7) << 1;
    const ull* Wk = W + (size_t)(it*16 + kl*4)*16;
    const ull* p0 = Wk + ((pg6 + r2    ) & 15);
    const ull* p1 = Wk + ((pg6 + r2 + 2) & 15);
    const ull* p2 = Wk + ((pg6 + r2 + 4) & 15);
    float xs[4] = {xa.x, xa.y, xa.z, xa.w};
    #pragma unroll
    for (int j = 0; j < 4; ++j){
      ulonglong2 w0 = *(const ulonglong2*)(p0 + j*16);
      ulonglong2 w1 = *(const ulonglong2*)(p1 + j*16);
      ulonglong2 w2 = *(const ulonglong2*)(p2 + j*16);
      ull xd = dup2(xs[j]);
      acc[0]=fma2(xd,w0.x,acc[0]); acc[1]=fma2(xd,w0.y,acc[1]);
      acc[2]=fma2(xd,w1.x,acc[2]); acc[3]=fma2(xd,w1.y,acc[3]);
      acc[4]=fma2(xd,w2.x,acc[4]); acc[5]=fma2(xd,w2.y,acc[5]);
    }
    xa = xb; xb = xc;
  }
}

__device__ __forceinline__ void reduce6(ull (&acc)[6]){
  #pragma unroll
  for (int p = 0; p < 6; ++p){
    acc[p] = add2(acc[p], shx64(acc[p], 1));
    acc[p] = add2(acc[p], shx64(acc[p], 2));
  }
}

__global__ void __launch_bounds__(NT, 1)
act_kernel(const float* __restrict__ input, const float* __restrict__ Wih,
           const float* __restrict__ Whh, const float* __restrict__ bih,
           const float* __restrict__ bhh, const float* __restrict__ wpv,
           const float* __restrict__ bpv, float* __restrict__ out)
{
  extern __shared__ unsigned char smraw[];
  SM& s = *reinterpret_cast<SM*>(smraw);
  const int tid = threadIdx.x, blk = blockIdx.x;
  const int rg = blk >> 5, cg = blk & 31;
  const int row0 = rg*32, col0 = cg*24;
  const int lane = tid & 31, warp = tid >> 5;
  const int og = lane >> 2, kl = lane & 3;
  const int pg6 = (warp >> 2) * 6;          // 0 or 6 (pair group)
  const int rr  = (warp & 3)*8 + og;        // local row 0..31
  const int gr  = row0 + rr;                // global row

  // ---- one-time: stage weights swizzled (pairs along cols) ----
  for (int idx = tid; idx < 24*HH; idx += NT){
    int c = idx / HH, k = idx - c*HH;
    int p = c >> 1;
    int slot = (p + 2*((k>>2)&7)) & 15;
    ((float*)&s.whh[(size_t)k*16 + slot])[c & 1] = Whh[(size_t)(col0+c)*HH + k];
  }
  for (int idx = tid; idx < 24*DD; idx += NT){
    int c = idx / DD, k = idx - c*DD;
    int p = c >> 1;
    int slot = (p + 2*((k>>2)&7)) & 15;
    ((float*)&s.wih[(size_t)k*16 + slot])[c & 1] = Wih[(size_t)(col0+c)*(DD+1) + k];
  }
  if (tid < 24){
    s.flagw[tid] = Wih[(size_t)(col0+tid)*(DD+1) + DD];
    s.wp[tid]    = wpv[col0+tid];
    s.bias[tid]  = bih[col0+tid] + bhh[col0+tid];
  }
  if (tid < 128) s.pc[tid] = 0.f;
  for (int e = tid; e < 32*24; e += NT){
    int r2 = e/24, c2 = e - r2*24;
    g_hxi[0][row0+r2][col0+c2] = 0.f;
  }
  const float bp0 = bpv[0];
  int rb = 0;
  unsigned ep = g_flags[blk];   // epoch base persists across graph replays
  gbar(++ep);

  for (int t = 0; t < TT; ++t){
    if (tid < 128){ s.ah[tid]=0.f; s.sc[tid]=0.f; s.spc[tid]=0.f; s.mask[tid]=1; }
    for (int e = tid; e < 32*24; e += NT){ int r2=e/24, c2=e-r2*24; s.ahx[r2][c2]=0.f; }

    // ---- base = x_t @ W_ih^T + b_ih + b_hh (ponder-invariant) ----
    {
      ull acc[6] = {0,0,0,0,0,0};
      gemm6<16,false>(acc, input + ((size_t)t*128 + gr)*DD, s.wih, kl, pg6);
      reduce6(acc);
      if (kl < 3){
        int pr = kl*2, cc = (pg6 + pr)*2;
        float2 f0 = *(float2*)&acc[pr];
        float2 f1 = *(float2*)&acc[pr+1];
        s.base[rr][cc]   = f0.x + s.bias[cc];
        s.base[rr][cc+1] = f0.y + s.bias[cc+1];
        s.base[rr][cc+2] = f1.x + s.bias[cc+2];
        s.base[rr][cc+3] = f1.y + s.bias[cc+3];
      }
    }
    __syncthreads();

    // ---- ponder loop ----
    for (int n = 0; n < 8; ++n){
      ull acc[6] = {0,0,0,0,0,0};
      gemm6<48,true>(acc, &g_hxi[rb][gr][0], s.whh, kl, pg6);
      reduce6(acc);

      const float fl = (n == 0) ? 0.f : 1.f;
      if (kl < 3){
        int pr = kl*2, cc = (pg6 + pr)*2;
        float2 f0 = *(float2*)&acc[pr];
        float2 f1 = *(float2*)&acc[pr+1];
        float h0 = tanhf(f0.x + s.base[rr][cc]   + fl*s.flagw[cc]);
        float h1 = tanhf(f0.y + s.base[rr][cc+1] + fl*s.flagw[cc+1]);
        float h2 = tanhf(f1.x + s.base[rr][cc+2] + fl*s.flagw[cc+2]);
        float h3 = tanhf(f1.y + s.base[rr][cc+3] + fl*s.flagw[cc+3]);
        s.hxn[rr][cc] = h0; s.hxn[rr][cc+1] = h1;
        s.hxn[rr][cc+2] = h2; s.hxn[rr][cc+3] = h3;
        int gc = col0 + cc;
        float2 o0, o1;
        if (s.mask[gr]){ o0 = make_float2(h0,h1); o1 = make_float2(h2,h3); }
        else {
          o0 = __ldcg((const float2*)&g_hxi[rb][gr][gc]);
          o1 = __ldcg((const float2*)&g_hxi[rb][gr][gc+2]);
        }
        *(float2*)&g_hxi[rb^1][gr][gc]   = o0;
        *(float2*)&g_hxi[rb^1][gr][gc+2] = o1;
      }
      __syncthreads();
      if (tid < 32){
        float pd = 0.f;
        #pragma unroll
        for (int c = 0; c < 24; c++) pd = fmaf(s.hxn[tid][c], s.wp[c], pd);
        g_pd[(size_t)(n*128 + row0 + tid)*32 + cg] = pd;
      }
      gbar(++ep);

      // redundant identical scalar update on every block (fixed order)
      int nm = 0;
      if (tid < 128){
        const float4* pr4 = (const float4*)&g_pd[(size_t)(n*128 + tid)*32];
        float sum = 0.f;
        #pragma unroll
        for (int q = 0; q < 8; q++){
          float4 v4 = __ldcg(pr4 + q);
          sum += v4.x; sum += v4.y; sum += v4.z; sum += v4.w;
        }
        float h = 1.f/(1.f + expf(-(sum + bp0)));
        int   m  = s.mask[tid];
        float mf = m ? 1.f : 0.f;
        if (m) s.spc[tid] = -s.ah[tid];
        float ah2 = s.ah[tid] + mf*h;
        float p2  = h - fmaxf(ah2 - 1.f, 0.f);
        s.coef[tid] = mf*(1.f + p2);
        s.sc[tid]  += mf;
        s.ah[tid]   = ah2;
        int m2 = (ah2 < 0.99f);
        s.mask[tid] = m2;
        nm = m2;
      }
      int nlive = __syncthreads_or(nm);
      for (int e = tid; e < 32*24; e += NT){
        int r2 = e/24, c2 = e - r2*24;
        s.ahx[r2][c2] = fmaf(s.coef[row0+r2], s.hxn[r2][c2], s.ahx[r2][c2]);
      }
      __syncthreads();
      rb ^= 1;
      if (!nlive) break;
    }

    // ---- end of step: outputs + carry ----
    for (int e = tid; e < 32*24; e += NT){
      int r2 = e/24, c2 = e - r2*24;
      int gr2 = row0 + r2, gc2 = col0 + c2;
      float v = s.ahx[r2][c2] / s.sc[gr2];
      out[(size_t)(t*128 + gr2)*HH + gc2] = v;
      if (t == TT-1) out[OFF_HXLAST + (size_t)gr2*HH + gc2] = v;
      g_hxi[rb][gr2][gc2] = v;
    }
    if (blk == 0 && tid < 128){
      s.pc[tid] += s.spc[tid];
      out[OFF_STEPS + t*128 + tid] = s.sc[tid];
    }
    gbar(++ep);
  }

  if (blk == 0 && tid < 128) out[OFF_PC + tid] = s.pc[tid];
}

extern "C" void kernel_launch(void* const* d_in, const int* in_sizes, int n_in,
                              void* d_out, int out_size)
{
  const float* input = (const float*)d_in[0];
  const float* Wih   = (const float*)d_in[1];
  const float* Whh   = (const float*)d_in[2];
  const float* bih   = (const float*)d_in[3];
  const float* bhh   = (const float*)d_in[4];
  const float* wpv   = (const float*)d_in[5];
  const float* bpv   = (const float*)d_in[6];
  (void)in_sizes; (void)n_in; (void)out_size;

  cudaFuncSetAttribute(act_kernel, cudaFuncAttributeMaxDynamicSharedMemorySize, (int)sizeof(SM));
  act_kernel<<<GRIDN, NT, sizeof(SM)>>>(input, Wih, Whh, bih, bhh, wpv, bpv, (float*)d_out);
}